// round 3
// baseline (speedup 1.0000x reference)
#include <cuda_runtime.h>
#include <cuda_bf16.h>
#include <cstdint>

// B=2, N=2048, D=1024, H=16, HD=64
#define Bc 2
#define Nc 2048
#define Dc 1024
#define Hc 16
#define HDc 64

// ---------------- scratch (device globals; no allocation allowed) ----------------
__device__ float g_q[(size_t)Bc * Hc * Nc * HDc];   // (b,h,n,d) 16MB
__device__ float g_k[(size_t)Bc * Hc * Nc * HDc];   // pre-scaled by HD^-0.5
__device__ float g_v[(size_t)Bc * Hc * Nc * HDc];
__device__ float g_s[(size_t)Bc * Hc * Nc * Nc];    // scores / attn, (b,h,n,m) 537MB, in-place
__device__ float g_o[(size_t)Bc * Nc * Hc * HDc];   // (b,n,h*hd) 16MB

// ---------------- SIMT SGEMM tiling ----------------
#define BM 128
#define BN 64
#define BK 16
#define TM 8
#define TN 4
// 256 threads = 16x16 (tx cols, ty rows)

__device__ __forceinline__ void mm_tile(const float (*As)[BM + 4], const float (*Bs)[BN + 4],
                                        float acc[TM][TN], int ty, int tx) {
#pragma unroll
    for (int kk = 0; kk < BK; kk++) {
        float a[TM], bb[TN];
        float4 a0 = *(const float4*)&As[kk][ty * TM];
        float4 a1 = *(const float4*)&As[kk][ty * TM + 4];
        a[0] = a0.x; a[1] = a0.y; a[2] = a0.z; a[3] = a0.w;
        a[4] = a1.x; a[5] = a1.y; a[6] = a1.z; a[7] = a1.w;
        float4 b0 = *(const float4*)&Bs[kk][tx * TN];
        bb[0] = b0.x; bb[1] = b0.y; bb[2] = b0.z; bb[3] = b0.w;
#pragma unroll
        for (int i = 0; i < TM; i++)
#pragma unroll
            for (int j = 0; j < TN; j++)
                acc[i][j] = fmaf(a[i], bb[j], acc[i][j]);
    }
}

// ---------------- kernel 1: QKV projections ----------------
__global__ void __launch_bounds__(256)
proj_kernel(const float* __restrict__ x, const float* __restrict__ Wq,
            const float* __restrict__ Wk, const float* __restrict__ Wv) {
    __shared__ float As[BK][BM + 4];
    __shared__ float Bs[BK][BN + 4];
    int which = blockIdx.z;
    const float* W = which == 0 ? Wq : (which == 1 ? Wk : Wv);
    float* dst = which == 0 ? g_q : (which == 1 ? g_k : g_v);
    float scale = (which == 1) ? 0.125f : 1.0f;  // HD^-0.5

    int tid = threadIdx.x;
    int tx = tid & 15, ty = tid >> 4;
    int row0 = blockIdx.y * BM, col0 = blockIdx.x * BN;

    float acc[TM][TN];
#pragma unroll
    for (int i = 0; i < TM; i++)
#pragma unroll
        for (int j = 0; j < TN; j++) acc[i][j] = 0.f;

    for (int kt = 0; kt < Dc; kt += BK) {
#pragma unroll
        for (int i = 0; i < 8; i++) {
            int idx = tid + i * 256;
            int m = idx >> 4, k = idx & 15;
            As[k][m] = x[(size_t)(row0 + m) * Dc + kt + k];
        }
#pragma unroll
        for (int i = 0; i < 4; i++) {
            int idx = tid + i * 256;
            int k = idx >> 6, n = idx & 63;
            Bs[k][n] = W[(size_t)(kt + k) * (Hc * HDc) + col0 + n];
        }
        __syncthreads();
        mm_tile(As, Bs, acc, ty, tx);
        __syncthreads();
    }
#pragma unroll
    for (int i = 0; i < TM; i++) {
        int row = row0 + ty * TM + i;
        int b = row >> 11, n = row & (Nc - 1);
#pragma unroll
        for (int j = 0; j < TN; j++) {
            int col = col0 + tx * TN + j;
            int h = col >> 6, d = col & 63;
            dst[(((size_t)b * Hc + h) * Nc + n) * HDc + d] = acc[i][j] * scale;
        }
    }
}

// ---------------- kernel 2: S = Q K^T per (b,h) ----------------
__global__ void __launch_bounds__(256) scores_kernel() {
    __shared__ float As[BK][BM + 4];
    __shared__ float Bs[BK][BN + 4];
    int bh = blockIdx.z;
    const float* Q = g_q + (size_t)bh * Nc * HDc;
    const float* Kc = g_k + (size_t)bh * Nc * HDc;
    int tid = threadIdx.x;
    int tx = tid & 15, ty = tid >> 4;
    int row0 = blockIdx.y * BM;   // n
    int col0 = blockIdx.x * BN;   // m

    float acc[TM][TN];
#pragma unroll
    for (int i = 0; i < TM; i++)
#pragma unroll
        for (int j = 0; j < TN; j++) acc[i][j] = 0.f;

    for (int kt = 0; kt < HDc; kt += BK) {
#pragma unroll
        for (int i = 0; i < 8; i++) {
            int idx = tid + i * 256;
            int m = idx >> 4, k = idx & 15;
            As[k][m] = Q[(size_t)(row0 + m) * HDc + kt + k];
        }
#pragma unroll
        for (int i = 0; i < 4; i++) {
            int idx = tid + i * 256;
            int n = idx >> 4, k = idx & 15;     // transpose-load K
            Bs[k][n] = Kc[(size_t)(col0 + n) * HDc + kt + k];
        }
        __syncthreads();
        mm_tile(As, Bs, acc, ty, tx);
        __syncthreads();
    }
#pragma unroll
    for (int i = 0; i < TM; i++) {
        int n = row0 + ty * TM + i;
#pragma unroll
        for (int j = 0; j < TN; j++) {
            int m = col0 + tx * TN + j;
            g_s[((size_t)bh * Nc + n) * Nc + m] = acc[i][j];
        }
    }
}

// ---------------- fast exp on FMA pipe (avoids MUFU bottleneck) ----------------
__device__ __forceinline__ float exp_fast(float x) {
    float y = fmaxf(x * 1.4426950408889634f, -125.0f);
    float r = y + 12582912.0f;
    int ir = __float_as_int(r) - 0x4B400000;
    float rf = r - 12582912.0f;
    float f = y - rf;
    float p = 1.5403530e-4f;
    p = fmaf(p, f, 1.3333558e-3f);
    p = fmaf(p, f, 9.6181291e-3f);
    p = fmaf(p, f, 5.5504109e-2f);
    p = fmaf(p, f, 2.4022651e-1f);
    p = fmaf(p, f, 6.9314718e-1f);
    p = fmaf(p, f, 1.0f);
    return p * __int_as_float((ir + 127) << 23);
}

// ---------------- kernel 3: L-mix -> softmax -> Wm-mix, fused, in-place ----------------
// One block per (b,n). smem holds S[b, :, n, :] = 16 x 2048 floats (128KB).
__global__ void __launch_bounds__(256)
talk_kernel(const float* __restrict__ Lm, const float* __restrict__ Wmm) {
    extern __shared__ float s[];                 // [16][2048]
    __shared__ float sL[256], sW[256];
    __shared__ float red[16 * 8];
    __shared__ float gmax[16], ginv[16];

    int tid = threadIdx.x;                       // 256 threads
    int lane = tid & 31, wid = tid >> 5;
    int bn = blockIdx.x;
    int b = bn >> 11, n = bn & (Nc - 1);
    const size_t HSTRIDE = (size_t)Nc * Nc;
    size_t base = ((size_t)b * Hc) * HSTRIDE + (size_t)n * Nc;

    sL[tid] = Lm[tid];
    sW[tid] = Wmm[tid];
    // vectorized tile load: 16 rows x 512 float4
    {
        const int NV = Nc / 4;                   // 512 float4 per row
        float4* s4 = (float4*)s;
        for (int idx = tid; idx < Hc * NV; idx += 256) {
            int h = idx / NV, c = idx - h * NV;
            const float4* src = (const float4*)(g_s + base + (size_t)h * HSTRIDE);
            s4[h * NV + c] = src[c];
        }
    }
    __syncthreads();

    // ---- pass 1: row max of t_g[m] = sum_h L[g,h] s[h][m] ----
    float lmax[16];
#pragma unroll
    for (int g = 0; g < 16; g++) lmax[g] = -3.0e38f;
    for (int j = 0; j < Nc / 256; j++) {
        int m = tid + j * 256;
        float sv[16];
#pragma unroll
        for (int h = 0; h < 16; h++) sv[h] = s[h * Nc + m];
#pragma unroll
        for (int g = 0; g < 16; g++) {
            float t = 0.f;
#pragma unroll
            for (int h = 0; h < 16; h++) t = fmaf(sL[g * 16 + h], sv[h], t);
            lmax[g] = fmaxf(lmax[g], t);
        }
    }
#pragma unroll
    for (int g = 0; g < 16; g++) {
        float v = lmax[g];
        for (int o = 16; o; o >>= 1) v = fmaxf(v, __shfl_xor_sync(0xFFFFFFFFu, v, o));
        if (lane == 0) red[g * 8 + wid] = v;
    }
    __syncthreads();
    if (tid < 16) {
        float v = red[tid * 8];
        for (int w = 1; w < 8; w++) v = fmaxf(v, red[tid * 8 + w]);
        gmax[tid] = v;
    }
    __syncthreads();

    // ---- pass 2: mix, exp, row sums; overwrite in place ----
    float gm[16], lsum[16];
#pragma unroll
    for (int g = 0; g < 16; g++) { gm[g] = gmax[g]; lsum[g] = 0.f; }
    for (int j = 0; j < Nc / 256; j++) {
        int m = tid + j * 256;
        float sv[16], pv[16];
#pragma unroll
        for (int h = 0; h < 16; h++) sv[h] = s[h * Nc + m];
#pragma unroll
        for (int g = 0; g < 16; g++) {
            float t = 0.f;
#pragma unroll
            for (int h = 0; h < 16; h++) t = fmaf(sL[g * 16 + h], sv[h], t);
            float p = exp_fast(t - gm[g]);
            lsum[g] += p;
            pv[g] = p;
        }
#pragma unroll
        for (int g = 0; g < 16; g++) s[g * Nc + m] = pv[g];
    }
#pragma unroll
    for (int g = 0; g < 16; g++) {
        float v = lsum[g];
        for (int o = 16; o; o >>= 1) v += __shfl_xor_sync(0xFFFFFFFFu, v, o);
        if (lane == 0) red[g * 8 + wid] = v;
    }
    __syncthreads();
    if (tid < 16) {
        float v = 0.f;
        for (int w = 0; w < 8; w++) v += red[tid * 8 + w];
        ginv[tid] = 1.0f / v;
    }
    __syncthreads();

    // ---- pass 3: normalize + Wm mix, write back (coalesced per-warp) ----
    float gi[16];
#pragma unroll
    for (int g = 0; g < 16; g++) gi[g] = ginv[g];
    for (int j = 0; j < Nc / 256; j++) {
        int m = tid + j * 256;
        float pv[16];
#pragma unroll
        for (int g = 0; g < 16; g++) pv[g] = s[g * Nc + m] * gi[g];
#pragma unroll
        for (int g2 = 0; g2 < 16; g2++) {
            float u = 0.f;
#pragma unroll
            for (int g = 0; g < 16; g++) u = fmaf(sW[g2 * 16 + g], pv[g], u);
            g_s[base + (size_t)g2 * HSTRIDE + m] = u;
        }
    }
}

// ---------------- kernel 4: O = attn @ V per (b,g) ----------------
__global__ void __launch_bounds__(256) av_kernel() {
    __shared__ float As[BK][BM + 4];
    __shared__ float Bs[BK][BN + 4];
    int bh = blockIdx.y;
    const float* U = g_s + (size_t)bh * Nc * Nc;
    const float* V = g_v + (size_t)bh * Nc * HDc;
    int tid = threadIdx.x;
    int tx = tid & 15, ty = tid >> 4;
    int row0 = blockIdx.x * BM;

    float acc[TM][TN];
#pragma unroll
    for (int i = 0; i < TM; i++)
#pragma unroll
        for (int j = 0; j < TN; j++) acc[i][j] = 0.f;

    for (int kt = 0; kt < Nc; kt += BK) {
#pragma unroll
        for (int i = 0; i < 8; i++) {
            int idx = tid + i * 256;
            int m = idx >> 4, k = idx & 15;
            As[k][m] = U[(size_t)(row0 + m) * Nc + kt + k];
        }
#pragma unroll
        for (int i = 0; i < 4; i++) {
            int idx = tid + i * 256;
            int k = idx >> 6, n = idx & 63;
            Bs[k][n] = V[(size_t)(kt + k) * HDc + n];
        }
        __syncthreads();
        mm_tile(As, Bs, acc, ty, tx);
        __syncthreads();
    }
    int b = bh >> 4, g = bh & 15;
#pragma unroll
    for (int i = 0; i < TM; i++) {
        int n = row0 + ty * TM + i;
#pragma unroll
        for (int j = 0; j < TN; j++) {
            int d = tx * TN + j;
            g_o[((size_t)b * Nc + n) * (Hc * HDc) + g * HDc + d] = acc[i][j];
        }
    }
}

// ---------------- kernel 5: out = g_o @ Wo + bo ----------------
__global__ void __launch_bounds__(256)
out_kernel(const float* __restrict__ Wo, const float* __restrict__ bo,
           float* __restrict__ out) {
    __shared__ float As[BK][BM + 4];
    __shared__ float Bs[BK][BN + 4];
    int tid = threadIdx.x;
    int tx = tid & 15, ty = tid >> 4;
    int row0 = blockIdx.y * BM, col0 = blockIdx.x * BN;

    float acc[TM][TN];
#pragma unroll
    for (int i = 0; i < TM; i++)
#pragma unroll
        for (int j = 0; j < TN; j++) acc[i][j] = 0.f;

    for (int kt = 0; kt < Hc * HDc; kt += BK) {
#pragma unroll
        for (int i = 0; i < 8; i++) {
            int idx = tid + i * 256;
            int m = idx >> 4, k = idx & 15;
            As[k][m] = g_o[(size_t)(row0 + m) * (Hc * HDc) + kt + k];
        }
#pragma unroll
        for (int i = 0; i < 4; i++) {
            int idx = tid + i * 256;
            int k = idx >> 6, n = idx & 63;
            Bs[k][n] = Wo[(size_t)(kt + k) * Dc + col0 + n];
        }
        __syncthreads();
        mm_tile(As, Bs, acc, ty, tx);
        __syncthreads();
    }
#pragma unroll
    for (int i = 0; i < TM; i++) {
        int row = row0 + ty * TM + i;
#pragma unroll
        for (int j = 0; j < TN; j++) {
            int col = col0 + tx * TN + j;
            out[(size_t)row * Dc + col] = acc[i][j] + bo[col];
        }
    }
}

// ---------------- launch ----------------
extern "C" void kernel_launch(void* const* d_in, const int* in_sizes, int n_in,
                              void* d_out, int out_size) {
    const float* x  = (const float*)d_in[0];
    const float* Wq = (const float*)d_in[1];
    const float* Wk = (const float*)d_in[2];
    const float* Wv = (const float*)d_in[3];
    const float* L  = (const float*)d_in[4];
    const float* Wm = (const float*)d_in[5];
    const float* Wo = (const float*)d_in[6];
    const float* bo = (const float*)d_in[7];
    float* out = (float*)d_out;
    (void)in_sizes; (void)n_in; (void)out_size;

    // 1) QKV projections: M=4096, N=1024, K=1024, x3
    proj_kernel<<<dim3((Hc * HDc) / BN, (Bc * Nc) / BM, 3), 256>>>(x, Wq, Wk, Wv);

    // 2) scores per (b,h): M=2048(n), N=2048(m), K=64
    scores_kernel<<<dim3(Nc / BN, Nc / BM, Bc * Hc), 256>>>();

    // 3) fused L-mix + softmax + Wm-mix (in-place on g_s)
    const int TALK_SMEM = Hc * Nc * sizeof(float);  // 128KB
    (void)cudaFuncSetAttribute(talk_kernel, cudaFuncAttributeMaxDynamicSharedMemorySize, TALK_SMEM);
    talk_kernel<<<Bc * Nc, 256, TALK_SMEM>>>(L, Wm);

    // 4) attn @ V per (b,g): M=2048(n), N=64(d), K=2048(m)
    av_kernel<<<dim3(Nc / BM, Bc * Hc), 256>>>();

    // 5) final projection + bias: M=4096, N=1024, K=1024
    out_kernel<<<dim3(Dc / BN, (Bc * Nc) / BM, 1), 256>>>(Wo, bo, out);
}

// round 4
// speedup vs baseline: 1.1347x; 1.1347x over previous
#include <cuda_runtime.h>
#include <cuda_bf16.h>
#include <cstdint>

// B=2, N=2048, D=1024, H=16, HD=64
#define Bc 2
#define Nc 2048
#define Dc 1024
#define Hc 16
#define HDc 64

// ---------------- scratch (device globals; no allocation allowed) ----------------
__device__ float g_q[(size_t)Bc * Hc * Nc * HDc];   // (b,h,n,d) 16MB
__device__ float g_k[(size_t)Bc * Hc * Nc * HDc];   // pre-scaled by HD^-0.5
__device__ float g_v[(size_t)Bc * Hc * Nc * HDc];
__device__ float g_s[(size_t)Bc * Hc * Nc * Nc];    // scores / attn, (b,h,n,m) 537MB, in-place
__device__ float g_o[(size_t)Bc * Nc * Hc * HDc];   // (b,n,h*hd) 16MB

// ---------------- tf32 helpers ----------------
__device__ __forceinline__ uint32_t f2tf(float f) {
    uint32_t u;
    asm("cvt.rna.tf32.f32 %0, %1;" : "=r"(u) : "f"(f));
    return u;
}
__device__ __forceinline__ void split_tf(float f, uint32_t& hi, uint32_t& lo) {
    hi = f2tf(f);
    lo = f2tf(f - __uint_as_float(hi));
}
__device__ __forceinline__ void mma8(float& c0, float& c1, float& c2, float& c3,
                                     uint32_t a0, uint32_t a1, uint32_t a2, uint32_t a3,
                                     uint32_t b0, uint32_t b1) {
    asm volatile(
        "mma.sync.aligned.m16n8k8.row.col.f32.tf32.tf32.f32 "
        "{%0,%1,%2,%3}, {%4,%5,%6,%7}, {%8,%9}, {%0,%1,%2,%3};"
        : "+f"(c0), "+f"(c1), "+f"(c2), "+f"(c3)
        : "r"(a0), "r"(a1), "r"(a2), "r"(a3), "r"(b0), "r"(b1));
}

// =======================================================================
// kernel 1: QKV projections, 3xTF32. C[4096,1024] = x @ W, permuted store.
// Block 128x128, BK=16, 256 thr, 8 warps as 2(m64) x 4(n32).
// =======================================================================
__global__ void __launch_bounds__(256, 1)
proj_tf32(const float* __restrict__ x, const float* __restrict__ Wq,
          const float* __restrict__ Wk, const float* __restrict__ Wv) {
    __shared__ uint32_t Ah[16][136], Al[16][136], Bh[16][136], Bl[16][136];
    int which = blockIdx.z;
    const float* W = which == 0 ? Wq : (which == 1 ? Wk : Wv);
    float* dst = which == 0 ? g_q : (which == 1 ? g_k : g_v);
    float scale = (which == 1) ? 0.125f : 1.0f;

    int tid = threadIdx.x, lane = tid & 31, w = tid >> 5;
    int wm = (w & 1) * 64, wn = (w >> 1) * 32;
    int row0 = blockIdx.y * 128, col0 = blockIdx.x * 128;

    float acc[4][4][4];
#pragma unroll
    for (int a = 0; a < 4; a++)
#pragma unroll
        for (int b = 0; b < 4; b++)
#pragma unroll
            for (int c = 0; c < 4; c++) acc[a][b][c] = 0.f;

    for (int kt = 0; kt < Dc; kt += 16) {
#pragma unroll
        for (int i = 0; i < 8; i++) {
            int idx = tid + i * 256;
            int m = idx >> 4, k = idx & 15;
            split_tf(x[(size_t)(row0 + m) * Dc + kt + k], Ah[k][m], Al[k][m]);
        }
#pragma unroll
        for (int i = 0; i < 8; i++) {
            int idx = tid + i * 256;
            int k = idx >> 7, n = idx & 127;
            split_tf(W[(size_t)(kt + k) * (Hc * HDc) + col0 + n], Bh[k][n], Bl[k][n]);
        }
        __syncthreads();
#pragma unroll
        for (int kk = 0; kk < 16; kk += 8) {
            int kr = kk + (lane & 3);
            int rr = lane >> 2;
            uint32_t ah[4][4], al[4][4], bh[4][2], bl[4][2];
#pragma unroll
            for (int mi = 0; mi < 4; mi++) {
                int rb = wm + mi * 16 + rr;
                ah[mi][0] = Ah[kr][rb];       al[mi][0] = Al[kr][rb];
                ah[mi][1] = Ah[kr][rb + 8];   al[mi][1] = Al[kr][rb + 8];
                ah[mi][2] = Ah[kr + 4][rb];   al[mi][2] = Al[kr + 4][rb];
                ah[mi][3] = Ah[kr + 4][rb + 8]; al[mi][3] = Al[kr + 4][rb + 8];
            }
#pragma unroll
            for (int ni = 0; ni < 4; ni++) {
                int nb = wn + ni * 8 + rr;
                bh[ni][0] = Bh[kr][nb];       bl[ni][0] = Bl[kr][nb];
                bh[ni][1] = Bh[kr + 4][nb];   bl[ni][1] = Bl[kr + 4][nb];
            }
#pragma unroll
            for (int mi = 0; mi < 4; mi++)
#pragma unroll
                for (int ni = 0; ni < 4; ni++) {
                    float* c = acc[mi][ni];
                    mma8(c[0], c[1], c[2], c[3], ah[mi][0], ah[mi][1], ah[mi][2], ah[mi][3], bh[ni][0], bh[ni][1]);
                    mma8(c[0], c[1], c[2], c[3], ah[mi][0], ah[mi][1], ah[mi][2], ah[mi][3], bl[ni][0], bl[ni][1]);
                    mma8(c[0], c[1], c[2], c[3], al[mi][0], al[mi][1], al[mi][2], al[mi][3], bh[ni][0], bh[ni][1]);
                }
        }
        __syncthreads();
    }
#pragma unroll
    for (int mi = 0; mi < 4; mi++) {
        int r0 = row0 + wm + mi * 16 + (lane >> 2);
        int r1 = r0 + 8;
        int b0i = r0 >> 11, n0i = r0 & (Nc - 1);
        int b1i = r1 >> 11, n1i = r1 & (Nc - 1);
#pragma unroll
        for (int ni = 0; ni < 4; ni++) {
            int c = col0 + wn + ni * 8 + (lane & 3) * 2;
            int h = c >> 6, d = c & 63;
            float2 v0 = {acc[mi][ni][0] * scale, acc[mi][ni][1] * scale};
            float2 v1 = {acc[mi][ni][2] * scale, acc[mi][ni][3] * scale};
            *(float2*)&dst[(((size_t)b0i * Hc + h) * Nc + n0i) * HDc + d] = v0;
            *(float2*)&dst[(((size_t)b1i * Hc + h) * Nc + n1i) * HDc + d] = v1;
        }
    }
}

// =======================================================================
// kernel 2: S = Q K^T per (b,h), single tf32 (error damped by softmax).
// Block 128(n) x 128(m), BK=16, K=64.
// =======================================================================
__global__ void __launch_bounds__(256, 2) scores_tf32() {
    __shared__ uint32_t Ah[16][136], Bh[16][136];
    int bh_ = blockIdx.z;
    const float* Q = g_q + (size_t)bh_ * Nc * HDc;
    const float* Kc = g_k + (size_t)bh_ * Nc * HDc;

    int tid = threadIdx.x, lane = tid & 31, w = tid >> 5;
    int wm = (w & 1) * 64, wn = (w >> 1) * 32;
    int row0 = blockIdx.y * 128, col0 = blockIdx.x * 128;

    float acc[4][4][4];
#pragma unroll
    for (int a = 0; a < 4; a++)
#pragma unroll
        for (int b = 0; b < 4; b++)
#pragma unroll
            for (int c = 0; c < 4; c++) acc[a][b][c] = 0.f;

    for (int kt = 0; kt < HDc; kt += 16) {
#pragma unroll
        for (int i = 0; i < 8; i++) {
            int idx = tid + i * 256;
            int m = idx >> 4, k = idx & 15;
            Ah[k][m] = f2tf(Q[(size_t)(row0 + m) * HDc + kt + k]);
        }
#pragma unroll
        for (int i = 0; i < 8; i++) {
            int idx = tid + i * 256;
            int n = idx >> 4, k = idx & 15;
            Bh[k][n] = f2tf(Kc[(size_t)(col0 + n) * HDc + kt + k]);
        }
        __syncthreads();
#pragma unroll
        for (int kk = 0; kk < 16; kk += 8) {
            int kr = kk + (lane & 3);
            int rr = lane >> 2;
            uint32_t ah[4][4], bh[4][2];
#pragma unroll
            for (int mi = 0; mi < 4; mi++) {
                int rb = wm + mi * 16 + rr;
                ah[mi][0] = Ah[kr][rb];
                ah[mi][1] = Ah[kr][rb + 8];
                ah[mi][2] = Ah[kr + 4][rb];
                ah[mi][3] = Ah[kr + 4][rb + 8];
            }
#pragma unroll
            for (int ni = 0; ni < 4; ni++) {
                int nb = wn + ni * 8 + rr;
                bh[ni][0] = Bh[kr][nb];
                bh[ni][1] = Bh[kr + 4][nb];
            }
#pragma unroll
            for (int mi = 0; mi < 4; mi++)
#pragma unroll
                for (int ni = 0; ni < 4; ni++) {
                    float* c = acc[mi][ni];
                    mma8(c[0], c[1], c[2], c[3], ah[mi][0], ah[mi][1], ah[mi][2], ah[mi][3], bh[ni][0], bh[ni][1]);
                }
        }
        __syncthreads();
    }
    size_t base = (size_t)bh_ * Nc * Nc;
#pragma unroll
    for (int mi = 0; mi < 4; mi++) {
        int r0 = row0 + wm + mi * 16 + (lane >> 2);
        int r1 = r0 + 8;
#pragma unroll
        for (int ni = 0; ni < 4; ni++) {
            int c = col0 + wn + ni * 8 + (lane & 3) * 2;
            float2 v0 = {acc[mi][ni][0], acc[mi][ni][1]};
            float2 v1 = {acc[mi][ni][2], acc[mi][ni][3]};
            *(float2*)&g_s[base + (size_t)r0 * Nc + c] = v0;
            *(float2*)&g_s[base + (size_t)r1 * Nc + c] = v1;
        }
    }
}

// ---------------- fast exp on FMA pipe ----------------
__device__ __forceinline__ float exp_fast(float x) {
    float y = fmaxf(x * 1.4426950408889634f, -125.0f);
    float r = y + 12582912.0f;
    int ir = __float_as_int(r) - 0x4B400000;
    float rf = r - 12582912.0f;
    float f = y - rf;
    float p = 1.5403530e-4f;
    p = fmaf(p, f, 1.3333558e-3f);
    p = fmaf(p, f, 9.6181291e-3f);
    p = fmaf(p, f, 5.5504109e-2f);
    p = fmaf(p, f, 2.4022651e-1f);
    p = fmaf(p, f, 6.9314718e-1f);
    p = fmaf(p, f, 1.0f);
    return p * __int_as_float((ir + 127) << 23);
}

// ---------------- kernel 3: L-mix -> softmax -> Wm-mix, fused, in-place ----------------
__global__ void __launch_bounds__(256)
talk_kernel(const float* __restrict__ Lm, const float* __restrict__ Wmm) {
    extern __shared__ float s[];                 // [16][2048]
    __shared__ float sL[256], sW[256];
    __shared__ float red[16 * 8];
    __shared__ float gmax[16], ginv[16];

    int tid = threadIdx.x;
    int lane = tid & 31, wid = tid >> 5;
    int bn = blockIdx.x;
    int b = bn >> 11, n = bn & (Nc - 1);
    const size_t HSTRIDE = (size_t)Nc * Nc;
    size_t base = ((size_t)b * Hc) * HSTRIDE + (size_t)n * Nc;

    sL[tid] = Lm[tid];
    sW[tid] = Wmm[tid];
    {
        const int NV = Nc / 4;
        float4* s4 = (float4*)s;
        for (int idx = tid; idx < Hc * NV; idx += 256) {
            int h = idx / NV, c = idx - h * NV;
            const float4* src = (const float4*)(g_s + base + (size_t)h * HSTRIDE);
            s4[h * NV + c] = src[c];
        }
    }
    __syncthreads();

    float lmax[16];
#pragma unroll
    for (int g = 0; g < 16; g++) lmax[g] = -3.0e38f;
    for (int j = 0; j < Nc / 256; j++) {
        int m = tid + j * 256;
        float sv[16];
#pragma unroll
        for (int h = 0; h < 16; h++) sv[h] = s[h * Nc + m];
#pragma unroll
        for (int g = 0; g < 16; g++) {
            float t = 0.f;
#pragma unroll
            for (int h = 0; h < 16; h++) t = fmaf(sL[g * 16 + h], sv[h], t);
            lmax[g] = fmaxf(lmax[g], t);
        }
    }
#pragma unroll
    for (int g = 0; g < 16; g++) {
        float v = lmax[g];
        for (int o = 16; o; o >>= 1) v = fmaxf(v, __shfl_xor_sync(0xFFFFFFFFu, v, o));
        if (lane == 0) red[g * 8 + wid] = v;
    }
    __syncthreads();
    if (tid < 16) {
        float v = red[tid * 8];
        for (int w = 1; w < 8; w++) v = fmaxf(v, red[tid * 8 + w]);
        gmax[tid] = v;
    }
    __syncthreads();

    float gm[16], lsum[16];
#pragma unroll
    for (int g = 0; g < 16; g++) { gm[g] = gmax[g]; lsum[g] = 0.f; }
    for (int j = 0; j < Nc / 256; j++) {
        int m = tid + j * 256;
        float sv[16], pv[16];
#pragma unroll
        for (int h = 0; h < 16; h++) sv[h] = s[h * Nc + m];
#pragma unroll
        for (int g = 0; g < 16; g++) {
            float t = 0.f;
#pragma unroll
            for (int h = 0; h < 16; h++) t = fmaf(sL[g * 16 + h], sv[h], t);
            float p = exp_fast(t - gm[g]);
            lsum[g] += p;
            pv[g] = p;
        }
#pragma unroll
        for (int g = 0; g < 16; g++) s[g * Nc + m] = pv[g];
    }
#pragma unroll
    for (int g = 0; g < 16; g++) {
        float v = lsum[g];
        for (int o = 16; o; o >>= 1) v += __shfl_xor_sync(0xFFFFFFFFu, v, o);
        if (lane == 0) red[g * 8 + wid] = v;
    }
    __syncthreads();
    if (tid < 16) {
        float v = 0.f;
        for (int w = 0; w < 8; w++) v += red[tid * 8 + w];
        ginv[tid] = 1.0f / v;
    }
    __syncthreads();

    float gi[16];
#pragma unroll
    for (int g = 0; g < 16; g++) gi[g] = ginv[g];
    for (int j = 0; j < Nc / 256; j++) {
        int m = tid + j * 256;
        float pv[16];
#pragma unroll
        for (int g = 0; g < 16; g++) pv[g] = s[g * Nc + m] * gi[g];
#pragma unroll
        for (int g2 = 0; g2 < 16; g2++) {
            float u = 0.f;
#pragma unroll
            for (int g = 0; g < 16; g++) u = fmaf(sW[g2 * 16 + g], pv[g], u);
            g_s[base + (size_t)g2 * HSTRIDE + m] = u;
        }
    }
}

// =======================================================================
// kernel 4: O = attn @ V per (b,g), 3xTF32. Block 128(n) x 64(d), K=2048.
// 8 warps as 4(m32) x 2(n32).
// =======================================================================
__global__ void __launch_bounds__(256, 2) av_tf32() {
    __shared__ uint32_t Ah[16][136], Al[16][136], Bh[16][72], Bl[16][72];
    int bh_ = blockIdx.y;
    const float* U = g_s + (size_t)bh_ * Nc * Nc;
    const float* V = g_v + (size_t)bh_ * Nc * HDc;

    int tid = threadIdx.x, lane = tid & 31, w = tid >> 5;
    int wm = (w >> 1) * 32, wn = (w & 1) * 32;
    int row0 = blockIdx.x * 128;

    float acc[2][4][4];
#pragma unroll
    for (int a = 0; a < 2; a++)
#pragma unroll
        for (int b = 0; b < 4; b++)
#pragma unroll
            for (int c = 0; c < 4; c++) acc[a][b][c] = 0.f;

    for (int kt = 0; kt < Nc; kt += 16) {
#pragma unroll
        for (int i = 0; i < 8; i++) {
            int idx = tid + i * 256;
            int m = idx >> 4, k = idx & 15;
            split_tf(U[(size_t)(row0 + m) * Nc + kt + k], Ah[k][m], Al[k][m]);
        }
#pragma unroll
        for (int i = 0; i < 4; i++) {
            int idx = tid + i * 256;
            int k = idx >> 6, n = idx & 63;
            split_tf(V[(size_t)(kt + k) * HDc + n], Bh[k][n], Bl[k][n]);
        }
        __syncthreads();
#pragma unroll
        for (int kk = 0; kk < 16; kk += 8) {
            int kr = kk + (lane & 3);
            int rr = lane >> 2;
            uint32_t ah[2][4], al[2][4], bh[4][2], bl[4][2];
#pragma unroll
            for (int mi = 0; mi < 2; mi++) {
                int rb = wm + mi * 16 + rr;
                ah[mi][0] = Ah[kr][rb];       al[mi][0] = Al[kr][rb];
                ah[mi][1] = Ah[kr][rb + 8];   al[mi][1] = Al[kr][rb + 8];
                ah[mi][2] = Ah[kr + 4][rb];   al[mi][2] = Al[kr + 4][rb];
                ah[mi][3] = Ah[kr + 4][rb + 8]; al[mi][3] = Al[kr + 4][rb + 8];
            }
#pragma unroll
            for (int ni = 0; ni < 4; ni++) {
                int nb = wn + ni * 8 + rr;
                bh[ni][0] = Bh[kr][nb];       bl[ni][0] = Bl[kr][nb];
                bh[ni][1] = Bh[kr + 4][nb];   bl[ni][1] = Bl[kr + 4][nb];
            }
#pragma unroll
            for (int mi = 0; mi < 2; mi++)
#pragma unroll
                for (int ni = 0; ni < 4; ni++) {
                    float* c = acc[mi][ni];
                    mma8(c[0], c[1], c[2], c[3], ah[mi][0], ah[mi][1], ah[mi][2], ah[mi][3], bh[ni][0], bh[ni][1]);
                    mma8(c[0], c[1], c[2], c[3], ah[mi][0], ah[mi][1], ah[mi][2], ah[mi][3], bl[ni][0], bl[ni][1]);
                    mma8(c[0], c[1], c[2], c[3], al[mi][0], al[mi][1], al[mi][2], al[mi][3], bh[ni][0], bh[ni][1]);
                }
        }
        __syncthreads();
    }
    int b = bh_ >> 4, g = bh_ & 15;
#pragma unroll
    for (int mi = 0; mi < 2; mi++) {
        int r0 = row0 + wm + mi * 16 + (lane >> 2);
        int r1 = r0 + 8;
#pragma unroll
        for (int ni = 0; ni < 4; ni++) {
            int d = wn + ni * 8 + (lane & 3) * 2;
            float2 v0 = {acc[mi][ni][0], acc[mi][ni][1]};
            float2 v1 = {acc[mi][ni][2], acc[mi][ni][3]};
            *(float2*)&g_o[((size_t)b * Nc + r0) * (Hc * HDc) + g * HDc + d] = v0;
            *(float2*)&g_o[((size_t)b * Nc + r1) * (Hc * HDc) + g * HDc + d] = v1;
        }
    }
}

// =======================================================================
// kernel 5: out = g_o @ Wo + bo, 3xTF32. Block 128x128, K=1024.
// =======================================================================
__global__ void __launch_bounds__(256, 1)
out_tf32(const float* __restrict__ Wo, const float* __restrict__ bo,
         float* __restrict__ out) {
    __shared__ uint32_t Ah[16][136], Al[16][136], Bh[16][136], Bl[16][136];
    int tid = threadIdx.x, lane = tid & 31, w = tid >> 5;
    int wm = (w & 1) * 64, wn = (w >> 1) * 32;
    int row0 = blockIdx.y * 128, col0 = blockIdx.x * 128;

    float acc[4][4][4];
#pragma unroll
    for (int a = 0; a < 4; a++)
#pragma unroll
        for (int b = 0; b < 4; b++)
#pragma unroll
            for (int c = 0; c < 4; c++) acc[a][b][c] = 0.f;

    for (int kt = 0; kt < Hc * HDc; kt += 16) {
#pragma unroll
        for (int i = 0; i < 8; i++) {
            int idx = tid + i * 256;
            int m = idx >> 4, k = idx & 15;
            split_tf(g_o[(size_t)(row0 + m) * (Hc * HDc) + kt + k], Ah[k][m], Al[k][m]);
        }
#pragma unroll
        for (int i = 0; i < 8; i++) {
            int idx = tid + i * 256;
            int k = idx >> 7, n = idx & 127;
            split_tf(Wo[(size_t)(kt + k) * Dc + col0 + n], Bh[k][n], Bl[k][n]);
        }
        __syncthreads();
#pragma unroll
        for (int kk = 0; kk < 16; kk += 8) {
            int kr = kk + (lane & 3);
            int rr = lane >> 2;
            uint32_t ah[4][4], al[4][4], bh[4][2], bl[4][2];
#pragma unroll
            for (int mi = 0; mi < 4; mi++) {
                int rb = wm + mi * 16 + rr;
                ah[mi][0] = Ah[kr][rb];       al[mi][0] = Al[kr][rb];
                ah[mi][1] = Ah[kr][rb + 8];   al[mi][1] = Al[kr][rb + 8];
                ah[mi][2] = Ah[kr + 4][rb];   al[mi][2] = Al[kr + 4][rb];
                ah[mi][3] = Ah[kr + 4][rb + 8]; al[mi][3] = Al[kr + 4][rb + 8];
            }
#pragma unroll
            for (int ni = 0; ni < 4; ni++) {
                int nb = wn + ni * 8 + rr;
                bh[ni][0] = Bh[kr][nb];       bl[ni][0] = Bl[kr][nb];
                bh[ni][1] = Bh[kr + 4][nb];   bl[ni][1] = Bl[kr + 4][nb];
            }
#pragma unroll
            for (int mi = 0; mi < 4; mi++)
#pragma unroll
                for (int ni = 0; ni < 4; ni++) {
                    float* c = acc[mi][ni];
                    mma8(c[0], c[1], c[2], c[3], ah[mi][0], ah[mi][1], ah[mi][2], ah[mi][3], bh[ni][0], bh[ni][1]);
                    mma8(c[0], c[1], c[2], c[3], ah[mi][0], ah[mi][1], ah[mi][2], ah[mi][3], bl[ni][0], bl[ni][1]);
                    mma8(c[0], c[1], c[2], c[3], al[mi][0], al[mi][1], al[mi][2], al[mi][3], bh[ni][0], bh[ni][1]);
                }
        }
        __syncthreads();
    }
#pragma unroll
    for (int mi = 0; mi < 4; mi++) {
        int r0 = row0 + wm + mi * 16 + (lane >> 2);
        int r1 = r0 + 8;
#pragma unroll
        for (int ni = 0; ni < 4; ni++) {
            int c = col0 + wn + ni * 8 + (lane & 3) * 2;
            float2 bias = {bo[c], bo[c + 1]};
            float2 v0 = {acc[mi][ni][0] + bias.x, acc[mi][ni][1] + bias.y};
            float2 v1 = {acc[mi][ni][2] + bias.x, acc[mi][ni][3] + bias.y};
            *(float2*)&out[(size_t)r0 * Dc + c] = v0;
            *(float2*)&out[(size_t)r1 * Dc + c] = v1;
        }
    }
}

// ---------------- launch ----------------
extern "C" void kernel_launch(void* const* d_in, const int* in_sizes, int n_in,
                              void* d_out, int out_size) {
    const float* x  = (const float*)d_in[0];
    const float* Wq = (const float*)d_in[1];
    const float* Wk = (const float*)d_in[2];
    const float* Wv = (const float*)d_in[3];
    const float* L  = (const float*)d_in[4];
    const float* Wm = (const float*)d_in[5];
    const float* Wo = (const float*)d_in[6];
    const float* bo = (const float*)d_in[7];
    float* out = (float*)d_out;
    (void)in_sizes; (void)n_in; (void)out_size;

    // 1) QKV projections (tensor, 3xTF32)
    proj_tf32<<<dim3((Hc * HDc) / 128, (Bc * Nc) / 128, 3), 256>>>(x, Wq, Wk, Wv);

    // 2) scores per (b,h) (tensor, 1xTF32)
    scores_tf32<<<dim3(Nc / 128, Nc / 128, Bc * Hc), 256>>>();

    // 3) fused L-mix + softmax + Wm-mix (fp32, in-place on g_s)
    const int TALK_SMEM = Hc * Nc * sizeof(float);  // 128KB
    (void)cudaFuncSetAttribute(talk_kernel, cudaFuncAttributeMaxDynamicSharedMemorySize, TALK_SMEM);
    talk_kernel<<<Bc * Nc, 256, TALK_SMEM>>>(L, Wm);

    // 4) attn @ V per (b,g) (tensor, 3xTF32)
    av_tf32<<<dim3(Nc / 128, Bc * Hc), 256>>>();

    // 5) final projection + bias (tensor, 3xTF32)
    out_tf32<<<dim3(Dc / 128, (Bc * Nc) / 128), 256>>>(Wo, bo, out);
}

// round 5
// speedup vs baseline: 1.8227x; 1.6064x over previous
#include <cuda_runtime.h>
#include <cuda_bf16.h>
#include <cstdint>

// B=2, N=2048, D=1024, H=16, HD=64
#define Bc 2
#define Nc 2048
#define Dc 1024
#define Hc 16
#define HDc 64

// ---------------- scratch ----------------
__device__ float g_q[(size_t)Bc * Hc * Nc * HDc];
__device__ float g_k[(size_t)Bc * Hc * Nc * HDc];   // pre-scaled by HD^-0.5
__device__ float g_v[(size_t)Bc * Hc * Nc * HDc];
__device__ float g_s[(size_t)Bc * Hc * Nc * Nc];    // 537MB, in-place
__device__ float g_o[(size_t)Bc * Nc * Hc * HDc];

// ---------------- tf32 helpers ----------------
__device__ __forceinline__ uint32_t f2tf(float f) {
    uint32_t u;
    asm("cvt.rna.tf32.f32 %0, %1;" : "=r"(u) : "f"(f));
    return u;
}
__device__ __forceinline__ void mma8(float& c0, float& c1, float& c2, float& c3,
                                     uint32_t a0, uint32_t a1, uint32_t a2, uint32_t a3,
                                     uint32_t b0, uint32_t b1) {
    asm volatile(
        "mma.sync.aligned.m16n8k8.row.col.f32.tf32.tf32.f32 "
        "{%0,%1,%2,%3}, {%4,%5,%6,%7}, {%8,%9}, {%0,%1,%2,%3};"
        : "+f"(c0), "+f"(c1), "+f"(c2), "+f"(c3)
        : "r"(a0), "r"(a1), "r"(a2), "r"(a3), "r"(b0), "r"(b1));
}

// =======================================================================
// kernel 1: QKV projections, 1xTF32. Block 128x128, BK=16, 8 warps 2x4.
// =======================================================================
__global__ void __launch_bounds__(256, 2)
proj_tf32(const float* __restrict__ x, const float* __restrict__ Wq,
          const float* __restrict__ Wk, const float* __restrict__ Wv) {
    __shared__ uint32_t Ah[16][136], Bh[16][136];
    int which = blockIdx.z;
    const float* W = which == 0 ? Wq : (which == 1 ? Wk : Wv);
    float* dst = which == 0 ? g_q : (which == 1 ? g_k : g_v);
    float scale = (which == 1) ? 0.125f : 1.0f;

    int tid = threadIdx.x, lane = tid & 31, w = tid >> 5;
    int wm = (w & 1) * 64, wn = (w >> 1) * 32;
    int row0 = blockIdx.y * 128, col0 = blockIdx.x * 128;

    float acc[4][4][4];
#pragma unroll
    for (int a = 0; a < 4; a++)
#pragma unroll
        for (int b = 0; b < 4; b++)
#pragma unroll
            for (int c = 0; c < 4; c++) acc[a][b][c] = 0.f;

    for (int kt = 0; kt < Dc; kt += 16) {
        // A: 128 rows x 16 k = 512 float4
#pragma unroll
        for (int i = 0; i < 2; i++) {
            int idx = tid + i * 256;
            int m = idx >> 2, k4 = (idx & 3) * 4;
            float4 v4 = *(const float4*)&x[(size_t)(row0 + m) * Dc + kt + k4];
            Ah[k4][m] = f2tf(v4.x); Ah[k4 + 1][m] = f2tf(v4.y);
            Ah[k4 + 2][m] = f2tf(v4.z); Ah[k4 + 3][m] = f2tf(v4.w);
        }
        // B: 16 k x 128 n = 512 float4
#pragma unroll
        for (int i = 0; i < 2; i++) {
            int idx = tid + i * 256;
            int k = idx >> 5, n4 = (idx & 31) * 4;
            float4 v4 = *(const float4*)&W[(size_t)(kt + k) * (Hc * HDc) + col0 + n4];
            Bh[k][n4] = f2tf(v4.x); Bh[k][n4 + 1] = f2tf(v4.y);
            Bh[k][n4 + 2] = f2tf(v4.z); Bh[k][n4 + 3] = f2tf(v4.w);
        }
        __syncthreads();
#pragma unroll
        for (int kk = 0; kk < 16; kk += 8) {
            int kr = kk + (lane & 3);
            int rr = lane >> 2;
            uint32_t ah[4][4], bh[4][2];
#pragma unroll
            for (int mi = 0; mi < 4; mi++) {
                int rb = wm + mi * 16 + rr;
                ah[mi][0] = Ah[kr][rb];
                ah[mi][1] = Ah[kr][rb + 8];
                ah[mi][2] = Ah[kr + 4][rb];
                ah[mi][3] = Ah[kr + 4][rb + 8];
            }
#pragma unroll
            for (int ni = 0; ni < 4; ni++) {
                int nb = wn + ni * 8 + rr;
                bh[ni][0] = Bh[kr][nb];
                bh[ni][1] = Bh[kr + 4][nb];
            }
#pragma unroll
            for (int mi = 0; mi < 4; mi++)
#pragma unroll
                for (int ni = 0; ni < 4; ni++) {
                    float* c = acc[mi][ni];
                    mma8(c[0], c[1], c[2], c[3], ah[mi][0], ah[mi][1], ah[mi][2], ah[mi][3], bh[ni][0], bh[ni][1]);
                }
        }
        __syncthreads();
    }
#pragma unroll
    for (int mi = 0; mi < 4; mi++) {
        int r0 = row0 + wm + mi * 16 + (lane >> 2);
        int r1 = r0 + 8;
        int b0i = r0 >> 11, n0i = r0 & (Nc - 1);
        int b1i = r1 >> 11, n1i = r1 & (Nc - 1);
#pragma unroll
        for (int ni = 0; ni < 4; ni++) {
            int c = col0 + wn + ni * 8 + (lane & 3) * 2;
            int h = c >> 6, d = c & 63;
            float2 v0 = {acc[mi][ni][0] * scale, acc[mi][ni][1] * scale};
            float2 v1 = {acc[mi][ni][2] * scale, acc[mi][ni][3] * scale};
            *(float2*)&dst[(((size_t)b0i * Hc + h) * Nc + n0i) * HDc + d] = v0;
            *(float2*)&dst[(((size_t)b1i * Hc + h) * Nc + n1i) * HDc + d] = v1;
        }
    }
}

// =======================================================================
// kernel 2: S = Q K^T per (b,h), 1xTF32. Block 128x128, K=64.
// =======================================================================
__global__ void __launch_bounds__(256, 2) scores_tf32() {
    __shared__ uint32_t Ah[16][136], Bh[16][136];
    int bh_ = blockIdx.z;
    const float* Q = g_q + (size_t)bh_ * Nc * HDc;
    const float* Kc = g_k + (size_t)bh_ * Nc * HDc;

    int tid = threadIdx.x, lane = tid & 31, w = tid >> 5;
    int wm = (w & 1) * 64, wn = (w >> 1) * 32;
    int row0 = blockIdx.y * 128, col0 = blockIdx.x * 128;

    float acc[4][4][4];
#pragma unroll
    for (int a = 0; a < 4; a++)
#pragma unroll
        for (int b = 0; b < 4; b++)
#pragma unroll
            for (int c = 0; c < 4; c++) acc[a][b][c] = 0.f;

    for (int kt = 0; kt < HDc; kt += 16) {
#pragma unroll
        for (int i = 0; i < 2; i++) {
            int idx = tid + i * 256;
            int m = idx >> 2, k4 = (idx & 3) * 4;
            float4 v4 = *(const float4*)&Q[(size_t)(row0 + m) * HDc + kt + k4];
            Ah[k4][m] = f2tf(v4.x); Ah[k4 + 1][m] = f2tf(v4.y);
            Ah[k4 + 2][m] = f2tf(v4.z); Ah[k4 + 3][m] = f2tf(v4.w);
        }
#pragma unroll
        for (int i = 0; i < 2; i++) {
            int idx = tid + i * 256;
            int n = idx >> 2, k4 = (idx & 3) * 4;
            float4 v4 = *(const float4*)&Kc[(size_t)(col0 + n) * HDc + kt + k4];
            Bh[k4][n] = f2tf(v4.x); Bh[k4 + 1][n] = f2tf(v4.y);
            Bh[k4 + 2][n] = f2tf(v4.z); Bh[k4 + 3][n] = f2tf(v4.w);
        }
        __syncthreads();
#pragma unroll
        for (int kk = 0; kk < 16; kk += 8) {
            int kr = kk + (lane & 3);
            int rr = lane >> 2;
            uint32_t ah[4][4], bh[4][2];
#pragma unroll
            for (int mi = 0; mi < 4; mi++) {
                int rb = wm + mi * 16 + rr;
                ah[mi][0] = Ah[kr][rb];
                ah[mi][1] = Ah[kr][rb + 8];
                ah[mi][2] = Ah[kr + 4][rb];
                ah[mi][3] = Ah[kr + 4][rb + 8];
            }
#pragma unroll
            for (int ni = 0; ni < 4; ni++) {
                int nb = wn + ni * 8 + rr;
                bh[ni][0] = Bh[kr][nb];
                bh[ni][1] = Bh[kr + 4][nb];
            }
#pragma unroll
            for (int mi = 0; mi < 4; mi++)
#pragma unroll
                for (int ni = 0; ni < 4; ni++) {
                    float* c = acc[mi][ni];
                    mma8(c[0], c[1], c[2], c[3], ah[mi][0], ah[mi][1], ah[mi][2], ah[mi][3], bh[ni][0], bh[ni][1]);
                }
        }
        __syncthreads();
    }
    size_t base = (size_t)bh_ * Nc * Nc;
#pragma unroll
    for (int mi = 0; mi < 4; mi++) {
        int r0 = row0 + wm + mi * 16 + (lane >> 2);
        int r1 = r0 + 8;
#pragma unroll
        for (int ni = 0; ni < 4; ni++) {
            int c = col0 + wn + ni * 8 + (lane & 3) * 2;
            float2 v0 = {acc[mi][ni][0], acc[mi][ni][1]};
            float2 v1 = {acc[mi][ni][2], acc[mi][ni][3]};
            *(float2*)&g_s[base + (size_t)r0 * Nc + c] = v0;
            *(float2*)&g_s[base + (size_t)r1 * Nc + c] = v1;
        }
    }
}

// ---------------- fast exp on FMA pipe ----------------
__device__ __forceinline__ float exp_fast(float x) {
    float y = fmaxf(x * 1.4426950408889634f, -125.0f);
    float r = y + 12582912.0f;
    int ir = __float_as_int(r) - 0x4B400000;
    float rf = r - 12582912.0f;
    float f = y - rf;
    float p = 1.5403530e-4f;
    p = fmaf(p, f, 1.3333558e-3f);
    p = fmaf(p, f, 9.6181291e-3f);
    p = fmaf(p, f, 5.5504109e-2f);
    p = fmaf(p, f, 2.4022651e-1f);
    p = fmaf(p, f, 6.9314718e-1f);
    p = fmaf(p, f, 1.0f);
    return p * __int_as_float((ir + 127) << 23);
}

// ---------------- kernel 3: L-mix -> softmax -> Wm-mix, fused, in-place ----------------
// Pass 1 stores T = L*S back into smem (kills the re-mix in pass 2);
// 1/Z folded into Wm' so pass 3 is a single 16x16 mix.
__global__ void __launch_bounds__(256)
talk_kernel(const float* __restrict__ Lm, const float* __restrict__ Wmm) {
    extern __shared__ float s[];                 // [16][2048]
    __shared__ float sL[256], sW[256], sWp[256];
    __shared__ float red[16 * 8];
    __shared__ float gmax[16], ginv[16];

    int tid = threadIdx.x;
    int lane = tid & 31, wid = tid >> 5;
    int bn = blockIdx.x;
    int b = bn >> 11, n = bn & (Nc - 1);
    const size_t HSTRIDE = (size_t)Nc * Nc;
    size_t base = ((size_t)b * Hc) * HSTRIDE + (size_t)n * Nc;

    sL[tid] = Lm[tid];
    sW[tid] = Wmm[tid];
    {
        const int NV = Nc / 4;
        float4* s4 = (float4*)s;
        for (int idx = tid; idx < Hc * NV; idx += 256) {
            int h = idx / NV, c = idx - h * NV;
            const float4* src = (const float4*)(g_s + base + (size_t)h * HSTRIDE);
            s4[h * NV + c] = src[c];
        }
    }
    __syncthreads();

    // ---- pass 1: T_g[m] = sum_h L[g,h] s[h][m]; store T in place; track max ----
    float lmax[16];
#pragma unroll
    for (int g = 0; g < 16; g++) lmax[g] = -3.0e38f;
    for (int j = 0; j < Nc / 256; j++) {
        int m = tid + j * 256;
        float sv[16], tv[16];
#pragma unroll
        for (int h = 0; h < 16; h++) sv[h] = s[h * Nc + m];
#pragma unroll
        for (int g = 0; g < 16; g++) {
            float t = 0.f;
#pragma unroll
            for (int h = 0; h < 16; h++) t = fmaf(sL[g * 16 + h], sv[h], t);
            lmax[g] = fmaxf(lmax[g], t);
            tv[g] = t;
        }
#pragma unroll
        for (int g = 0; g < 16; g++) s[g * Nc + m] = tv[g];   // same column, same thread
    }
#pragma unroll
    for (int g = 0; g < 16; g++) {
        float v = lmax[g];
        for (int o = 16; o; o >>= 1) v = fmaxf(v, __shfl_xor_sync(0xFFFFFFFFu, v, o));
        if (lane == 0) red[g * 8 + wid] = v;
    }
    __syncthreads();
    if (tid < 16) {
        float v = red[tid * 8];
        for (int w = 1; w < 8; w++) v = fmaxf(v, red[tid * 8 + w]);
        gmax[tid] = v;
    }
    __syncthreads();

    // ---- pass 2: p = exp(T - max); store p in place; track sum ----
    float gm[16], lsum[16];
#pragma unroll
    for (int g = 0; g < 16; g++) { gm[g] = gmax[g]; lsum[g] = 0.f; }
    for (int j = 0; j < Nc / 256; j++) {
        int m = tid + j * 256;
#pragma unroll
        for (int g = 0; g < 16; g++) {
            float p = exp_fast(s[g * Nc + m] - gm[g]);
            lsum[g] += p;
            s[g * Nc + m] = p;
        }
    }
#pragma unroll
    for (int g = 0; g < 16; g++) {
        float v = lsum[g];
        for (int o = 16; o; o >>= 1) v += __shfl_xor_sync(0xFFFFFFFFu, v, o);
        if (lane == 0) red[g * 8 + wid] = v;
    }
    __syncthreads();
    if (tid < 16) {
        float v = 0.f;
        for (int w = 0; w < 8; w++) v += red[tid * 8 + w];
        ginv[tid] = 1.0f / v;
    }
    __syncthreads();
    // fold 1/Z into Wm
    sWp[tid] = sW[tid] * ginv[tid & 15];
    __syncthreads();

    // ---- pass 3: u_g2 = sum_g Wm'[g2,g] p_g; write to gmem ----
    for (int j = 0; j < Nc / 256; j++) {
        int m = tid + j * 256;
        float pv[16];
#pragma unroll
        for (int g = 0; g < 16; g++) pv[g] = s[g * Nc + m];
#pragma unroll
        for (int g2 = 0; g2 < 16; g2++) {
            float u = 0.f;
#pragma unroll
            for (int g = 0; g < 16; g++) u = fmaf(sWp[g2 * 16 + g], pv[g], u);
            g_s[base + (size_t)g2 * HSTRIDE + m] = u;
        }
    }
}

// =======================================================================
// kernel 4: O = attn @ V per (b,g), 1xTF32. Block 128(n) x 64(d), K=2048.
// =======================================================================
__global__ void __launch_bounds__(256, 3) av_tf32() {
    __shared__ uint32_t Ah[16][136], Bh[16][72];
    int bh_ = blockIdx.y;
    const float* U = g_s + (size_t)bh_ * Nc * Nc;
    const float* V = g_v + (size_t)bh_ * Nc * HDc;

    int tid = threadIdx.x, lane = tid & 31, w = tid >> 5;
    int wm = (w >> 1) * 32, wn = (w & 1) * 32;
    int row0 = blockIdx.x * 128;

    float acc[2][4][4];
#pragma unroll
    for (int a = 0; a < 2; a++)
#pragma unroll
        for (int b = 0; b < 4; b++)
#pragma unroll
            for (int c = 0; c < 4; c++) acc[a][b][c] = 0.f;

    for (int kt = 0; kt < Nc; kt += 16) {
        // U: 128 rows x 16 k = 512 float4
#pragma unroll
        for (int i = 0; i < 2; i++) {
            int idx = tid + i * 256;
            int m = idx >> 2, k4 = (idx & 3) * 4;
            float4 v4 = *(const float4*)&U[(size_t)(row0 + m) * Nc + kt + k4];
            Ah[k4][m] = f2tf(v4.x); Ah[k4 + 1][m] = f2tf(v4.y);
            Ah[k4 + 2][m] = f2tf(v4.z); Ah[k4 + 3][m] = f2tf(v4.w);
        }
        // V: 16 k x 64 n = 256 float4
        {
            int k = tid >> 4, n4 = (tid & 15) * 4;
            float4 v4 = *(const float4*)&V[(size_t)(kt + k) * HDc + n4];
            Bh[k][n4] = f2tf(v4.x); Bh[k][n4 + 1] = f2tf(v4.y);
            Bh[k][n4 + 2] = f2tf(v4.z); Bh[k][n4 + 3] = f2tf(v4.w);
        }
        __syncthreads();
#pragma unroll
        for (int kk = 0; kk < 16; kk += 8) {
            int kr = kk + (lane & 3);
            int rr = lane >> 2;
            uint32_t ah[2][4], bh[4][2];
#pragma unroll
            for (int mi = 0; mi < 2; mi++) {
                int rb = wm + mi * 16 + rr;
                ah[mi][0] = Ah[kr][rb];
                ah[mi][1] = Ah[kr][rb + 8];
                ah[mi][2] = Ah[kr + 4][rb];
                ah[mi][3] = Ah[kr + 4][rb + 8];
            }
#pragma unroll
            for (int ni = 0; ni < 4; ni++) {
                int nb = wn + ni * 8 + rr;
                bh[ni][0] = Bh[kr][nb];
                bh[ni][1] = Bh[kr + 4][nb];
            }
#pragma unroll
            for (int mi = 0; mi < 2; mi++)
#pragma unroll
                for (int ni = 0; ni < 4; ni++) {
                    float* c = acc[mi][ni];
                    mma8(c[0], c[1], c[2], c[3], ah[mi][0], ah[mi][1], ah[mi][2], ah[mi][3], bh[ni][0], bh[ni][1]);
                }
        }
        __syncthreads();
    }
    int b = bh_ >> 4, g = bh_ & 15;
#pragma unroll
    for (int mi = 0; mi < 2; mi++) {
        int r0 = row0 + wm + mi * 16 + (lane >> 2);
        int r1 = r0 + 8;
#pragma unroll
        for (int ni = 0; ni < 4; ni++) {
            int d = wn + ni * 8 + (lane & 3) * 2;
            float2 v0 = {acc[mi][ni][0], acc[mi][ni][1]};
            float2 v1 = {acc[mi][ni][2], acc[mi][ni][3]};
            *(float2*)&g_o[((size_t)b * Nc + r0) * (Hc * HDc) + g * HDc + d] = v0;
            *(float2*)&g_o[((size_t)b * Nc + r1) * (Hc * HDc) + g * HDc + d] = v1;
        }
    }
}

// =======================================================================
// kernel 5: out = g_o @ Wo + bo, 1xTF32. Block 128x128, K=1024.
// =======================================================================
__global__ void __launch_bounds__(256, 2)
out_tf32(const float* __restrict__ Wo, const float* __restrict__ bo,
         float* __restrict__ out) {
    __shared__ uint32_t Ah[16][136], Bh[16][136];
    int tid = threadIdx.x, lane = tid & 31, w = tid >> 5;
    int wm = (w & 1) * 64, wn = (w >> 1) * 32;
    int row0 = blockIdx.y * 128, col0 = blockIdx.x * 128;

    float acc[4][4][4];
#pragma unroll
    for (int a = 0; a < 4; a++)
#pragma unroll
        for (int b = 0; b < 4; b++)
#pragma unroll
            for (int c = 0; c < 4; c++) acc[a][b][c] = 0.f;

    for (int kt = 0; kt < Hc * HDc; kt += 16) {
#pragma unroll
        for (int i = 0; i < 2; i++) {
            int idx = tid + i * 256;
            int m = idx >> 2, k4 = (idx & 3) * 4;
            float4 v4 = *(const float4*)&g_o[(size_t)(row0 + m) * (Hc * HDc) + kt + k4];
            Ah[k4][m] = f2tf(v4.x); Ah[k4 + 1][m] = f2tf(v4.y);
            Ah[k4 + 2][m] = f2tf(v4.z); Ah[k4 + 3][m] = f2tf(v4.w);
        }
#pragma unroll
        for (int i = 0; i < 2; i++) {
            int idx = tid + i * 256;
            int k = idx >> 5, n4 = (idx & 31) * 4;
            float4 v4 = *(const float4*)&Wo[(size_t)(kt + k) * Dc + col0 + n4];
            Bh[k][n4] = f2tf(v4.x); Bh[k][n4 + 1] = f2tf(v4.y);
            Bh[k][n4 + 2] = f2tf(v4.z); Bh[k][n4 + 3] = f2tf(v4.w);
        }
        __syncthreads();
#pragma unroll
        for (int kk = 0; kk < 16; kk += 8) {
            int kr = kk + (lane & 3);
            int rr = lane >> 2;
            uint32_t ah[4][4], bh[4][2];
#pragma unroll
            for (int mi = 0; mi < 4; mi++) {
                int rb = wm + mi * 16 + rr;
                ah[mi][0] = Ah[kr][rb];
                ah[mi][1] = Ah[kr][rb + 8];
                ah[mi][2] = Ah[kr + 4][rb];
                ah[mi][3] = Ah[kr + 4][rb + 8];
            }
#pragma unroll
            for (int ni = 0; ni < 4; ni++) {
                int nb = wn + ni * 8 + rr;
                bh[ni][0] = Bh[kr][nb];
                bh[ni][1] = Bh[kr + 4][nb];
            }
#pragma unroll
            for (int mi = 0; mi < 4; mi++)
#pragma unroll
                for (int ni = 0; ni < 4; ni++) {
                    float* c = acc[mi][ni];
                    mma8(c[0], c[1], c[2], c[3], ah[mi][0], ah[mi][1], ah[mi][2], ah[mi][3], bh[ni][0], bh[ni][1]);
                }
        }
        __syncthreads();
    }
#pragma unroll
    for (int mi = 0; mi < 4; mi++) {
        int r0 = row0 + wm + mi * 16 + (lane >> 2);
        int r1 = r0 + 8;
#pragma unroll
        for (int ni = 0; ni < 4; ni++) {
            int c = col0 + wn + ni * 8 + (lane & 3) * 2;
            float2 bias = {bo[c], bo[c + 1]};
            float2 v0 = {acc[mi][ni][0] + bias.x, acc[mi][ni][1] + bias.y};
            float2 v1 = {acc[mi][ni][2] + bias.x, acc[mi][ni][3] + bias.y};
            *(float2*)&out[(size_t)r0 * Dc + c] = v0;
            *(float2*)&out[(size_t)r1 * Dc + c] = v1;
        }
    }
}

// ---------------- launch ----------------
extern "C" void kernel_launch(void* const* d_in, const int* in_sizes, int n_in,
                              void* d_out, int out_size) {
    const float* x  = (const float*)d_in[0];
    const float* Wq = (const float*)d_in[1];
    const float* Wk = (const float*)d_in[2];
    const float* Wv = (const float*)d_in[3];
    const float* L  = (const float*)d_in[4];
    const float* Wm = (const float*)d_in[5];
    const float* Wo = (const float*)d_in[6];
    const float* bo = (const float*)d_in[7];
    float* out = (float*)d_out;
    (void)in_sizes; (void)n_in; (void)out_size;

    proj_tf32<<<dim3((Hc * HDc) / 128, (Bc * Nc) / 128, 3), 256>>>(x, Wq, Wk, Wv);

    scores_tf32<<<dim3(Nc / 128, Nc / 128, Bc * Hc), 256>>>();

    const int TALK_SMEM = Hc * Nc * sizeof(float);  // 128KB
    (void)cudaFuncSetAttribute(talk_kernel, cudaFuncAttributeMaxDynamicSharedMemorySize, TALK_SMEM);
    talk_kernel<<<Bc * Nc, 256, TALK_SMEM>>>(L, Wm);

    av_tf32<<<dim3(Nc / 128, Bc * Hc), 256>>>();

    out_tf32<<<dim3(Dc / 128, (Bc * Nc) / 128), 256>>>(Wo, bo, out);
}

// round 6
// speedup vs baseline: 2.1172x; 1.1616x over previous
#include <cuda_runtime.h>
#include <cuda_fp16.h>
#include <cstdint>

// B=2, N=2048, D=1024, H=16, HD=64
#define Bc 2
#define Nc 2048
#define Dc 1024
#define Hc 16
#define HDc 64

// ---------------- scratch (fp16 inter-kernel tensors) ----------------
__device__ __half g_q[(size_t)Bc * Hc * Nc * HDc];
__device__ __half g_k[(size_t)Bc * Hc * Nc * HDc];   // pre-scaled by HD^-0.5
__device__ __half g_v[(size_t)Bc * Hc * Nc * HDc];
__device__ __half g_s[(size_t)Bc * Hc * Nc * Nc];    // 268MB, in-place
__device__ __half g_o[(size_t)Bc * Nc * Hc * HDc];

// ---------------- helpers ----------------
__device__ __forceinline__ uint32_t pack2(float a, float b) {
    __half2 h = __floats2half2_rn(a, b);
    return *(uint32_t*)&h;
}
__device__ __forceinline__ void mma16(float& c0, float& c1, float& c2, float& c3,
                                      uint32_t a0, uint32_t a1, uint32_t a2, uint32_t a3,
                                      uint32_t b0, uint32_t b1) {
    asm volatile(
        "mma.sync.aligned.m16n8k16.row.col.f32.f16.f16.f32 "
        "{%0,%1,%2,%3}, {%4,%5,%6,%7}, {%8,%9}, {%0,%1,%2,%3};"
        : "+f"(c0), "+f"(c1), "+f"(c2), "+f"(c3)
        : "r"(a0), "r"(a1), "r"(a2), "r"(a3), "r"(b0), "r"(b1));
}

// =======================================================================
// kernel 1: QKV projections, fp16 MMA. Block 128x128, BK=16, 8 warps 2x4.
// smem layout: X2[kp][m] = half2(A[m,2kp], A[m,2kp+1]), kp=0..7.
// =======================================================================
__global__ void __launch_bounds__(256, 2)
proj_f16(const float* __restrict__ x, const float* __restrict__ Wq,
         const float* __restrict__ Wk, const float* __restrict__ Wv) {
    __shared__ uint32_t Ah2[8][132], Bh2[8][132];
    int which = blockIdx.z;
    const float* W = which == 0 ? Wq : (which == 1 ? Wk : Wv);
    __half* dst = which == 0 ? g_q : (which == 1 ? g_k : g_v);
    float scale = (which == 1) ? 0.125f : 1.0f;

    int tid = threadIdx.x, lane = tid & 31, w = tid >> 5;
    int wm = (w & 1) * 64, wn = (w >> 1) * 32;
    int row0 = blockIdx.y * 128, col0 = blockIdx.x * 128;

    float acc[4][4][4];
#pragma unroll
    for (int a = 0; a < 4; a++)
#pragma unroll
        for (int b = 0; b < 4; b++)
#pragma unroll
            for (int c = 0; c < 4; c++) acc[a][b][c] = 0.f;

    for (int kt = 0; kt < Dc; kt += 16) {
        // A: x fp32 -> half2 pairs along k
#pragma unroll
        for (int i = 0; i < 2; i++) {
            int idx = tid + i * 256;
            int m = idx >> 2, k4 = (idx & 3) * 4;
            float4 v4 = *(const float4*)&x[(size_t)(row0 + m) * Dc + kt + k4];
            Ah2[k4 >> 1][m] = pack2(v4.x, v4.y);
            Ah2[(k4 >> 1) + 1][m] = pack2(v4.z, v4.w);
        }
        // B: W fp32, pair across two k rows
        {
            int kp = tid >> 5, n4 = (tid & 31) * 4;
            float4 f0 = *(const float4*)&W[(size_t)(kt + 2 * kp) * (Hc * HDc) + col0 + n4];
            float4 f1 = *(const float4*)&W[(size_t)(kt + 2 * kp + 1) * (Hc * HDc) + col0 + n4];
            uint4 st = {pack2(f0.x, f1.x), pack2(f0.y, f1.y), pack2(f0.z, f1.z), pack2(f0.w, f1.w)};
            *(uint4*)&Bh2[kp][n4] = st;
        }
        __syncthreads();
        int kr = lane & 3, rr = lane >> 2;
        uint32_t ah[4][4], bh[4][2];
#pragma unroll
        for (int mi = 0; mi < 4; mi++) {
            int rb = wm + mi * 16 + rr;
            ah[mi][0] = Ah2[kr][rb];
            ah[mi][1] = Ah2[kr][rb + 8];
            ah[mi][2] = Ah2[kr + 4][rb];
            ah[mi][3] = Ah2[kr + 4][rb + 8];
        }
#pragma unroll
        for (int ni = 0; ni < 4; ni++) {
            int nb = wn + ni * 8 + rr;
            bh[ni][0] = Bh2[kr][nb];
            bh[ni][1] = Bh2[kr + 4][nb];
        }
#pragma unroll
        for (int mi = 0; mi < 4; mi++)
#pragma unroll
            for (int ni = 0; ni < 4; ni++) {
                float* c = acc[mi][ni];
                mma16(c[0], c[1], c[2], c[3], ah[mi][0], ah[mi][1], ah[mi][2], ah[mi][3], bh[ni][0], bh[ni][1]);
            }
        __syncthreads();
    }
#pragma unroll
    for (int mi = 0; mi < 4; mi++) {
        int r0 = row0 + wm + mi * 16 + (lane >> 2);
        int r1 = r0 + 8;
        int b0i = r0 >> 11, n0i = r0 & (Nc - 1);
        int b1i = r1 >> 11, n1i = r1 & (Nc - 1);
#pragma unroll
        for (int ni = 0; ni < 4; ni++) {
            int c = col0 + wn + ni * 8 + (lane & 3) * 2;
            int h = c >> 6, d = c & 63;
            __half2 v0 = __floats2half2_rn(acc[mi][ni][0] * scale, acc[mi][ni][1] * scale);
            __half2 v1 = __floats2half2_rn(acc[mi][ni][2] * scale, acc[mi][ni][3] * scale);
            *(__half2*)&dst[(((size_t)b0i * Hc + h) * Nc + n0i) * HDc + d] = v0;
            *(__half2*)&dst[(((size_t)b1i * Hc + h) * Nc + n1i) * HDc + d] = v1;
        }
    }
}

// =======================================================================
// kernel 2: S = Q K^T per (b,h), fp16 MMA. Block 128x128, K=64.
// =======================================================================
__global__ void __launch_bounds__(256, 2) scores_f16() {
    __shared__ uint32_t Ah2[8][132], Bh2[8][132];
    int bh_ = blockIdx.z;
    const __half* Q = g_q + (size_t)bh_ * Nc * HDc;
    const __half* Kc = g_k + (size_t)bh_ * Nc * HDc;

    int tid = threadIdx.x, lane = tid & 31, w = tid >> 5;
    int wm = (w & 1) * 64, wn = (w >> 1) * 32;
    int row0 = blockIdx.y * 128, col0 = blockIdx.x * 128;

    float acc[4][4][4];
#pragma unroll
    for (int a = 0; a < 4; a++)
#pragma unroll
        for (int b = 0; b < 4; b++)
#pragma unroll
            for (int c = 0; c < 4; c++) acc[a][b][c] = 0.f;

    for (int kt = 0; kt < HDc; kt += 16) {
        // A: Q fp16, 8 halves along k = 4 half2 direct
        {
            int m = tid >> 1, ko = (tid & 1) * 8;
            uint4 u = *(const uint4*)&Q[(size_t)(row0 + m) * HDc + kt + ko];
            Ah2[(ko >> 1) + 0][m] = u.x;
            Ah2[(ko >> 1) + 1][m] = u.y;
            Ah2[(ko >> 1) + 2][m] = u.z;
            Ah2[(ko >> 1) + 3][m] = u.w;
        }
        // B: K fp16, same layout (k along row)
        {
            int n = tid >> 1, ko = (tid & 1) * 8;
            uint4 u = *(const uint4*)&Kc[(size_t)(col0 + n) * HDc + kt + ko];
            Bh2[(ko >> 1) + 0][n] = u.x;
            Bh2[(ko >> 1) + 1][n] = u.y;
            Bh2[(ko >> 1) + 2][n] = u.z;
            Bh2[(ko >> 1) + 3][n] = u.w;
        }
        __syncthreads();
        int kr = lane & 3, rr = lane >> 2;
        uint32_t ah[4][4], bh[4][2];
#pragma unroll
        for (int mi = 0; mi < 4; mi++) {
            int rb = wm + mi * 16 + rr;
            ah[mi][0] = Ah2[kr][rb];
            ah[mi][1] = Ah2[kr][rb + 8];
            ah[mi][2] = Ah2[kr + 4][rb];
            ah[mi][3] = Ah2[kr + 4][rb + 8];
        }
#pragma unroll
        for (int ni = 0; ni < 4; ni++) {
            int nb = wn + ni * 8 + rr;
            bh[ni][0] = Bh2[kr][nb];
            bh[ni][1] = Bh2[kr + 4][nb];
        }
#pragma unroll
        for (int mi = 0; mi < 4; mi++)
#pragma unroll
            for (int ni = 0; ni < 4; ni++) {
                float* c = acc[mi][ni];
                mma16(c[0], c[1], c[2], c[3], ah[mi][0], ah[mi][1], ah[mi][2], ah[mi][3], bh[ni][0], bh[ni][1]);
            }
        __syncthreads();
    }
    size_t base = (size_t)bh_ * Nc * Nc;
#pragma unroll
    for (int mi = 0; mi < 4; mi++) {
        int r0 = row0 + wm + mi * 16 + (lane >> 2);
        int r1 = r0 + 8;
#pragma unroll
        for (int ni = 0; ni < 4; ni++) {
            int c = col0 + wn + ni * 8 + (lane & 3) * 2;
            *(__half2*)&g_s[base + (size_t)r0 * Nc + c] = __floats2half2_rn(acc[mi][ni][0], acc[mi][ni][1]);
            *(__half2*)&g_s[base + (size_t)r1 * Nc + c] = __floats2half2_rn(acc[mi][ni][2], acc[mi][ni][3]);
        }
    }
}

// ---------------- fast exp on FMA pipe ----------------
__device__ __forceinline__ float exp_fast(float x) {
    float y = fmaxf(x * 1.4426950408889634f, -125.0f);
    float r = y + 12582912.0f;
    int ir = __float_as_int(r) - 0x4B400000;
    float rf = r - 12582912.0f;
    float f = y - rf;
    float p = 1.5403530e-4f;
    p = fmaf(p, f, 1.3333558e-3f);
    p = fmaf(p, f, 9.6181291e-3f);
    p = fmaf(p, f, 5.5504109e-2f);
    p = fmaf(p, f, 2.4022651e-1f);
    p = fmaf(p, f, 6.9314718e-1f);
    p = fmaf(p, f, 1.0f);
    return p * __int_as_float((ir + 127) << 23);
}

// ---------------- kernel 3: L-mix -> softmax -> Wm-mix, fused, in-place ----------------
// fp16 gmem I/O, fp32 smem compute. One block per (b,n); smem 128KB.
__global__ void __launch_bounds__(256)
talk_kernel(const float* __restrict__ Lm, const float* __restrict__ Wmm) {
    extern __shared__ float s[];                 // [16][2048] fp32
    __shared__ float sL[256], sW[256], sWp[256];
    __shared__ float red[16 * 8];
    __shared__ float gmax[16], ginv[16];

    int tid = threadIdx.x;
    int lane = tid & 31, wid = tid >> 5;
    int bn = blockIdx.x;
    int b = bn >> 11, n = bn & (Nc - 1);
    const size_t HSTRIDE = (size_t)Nc * Nc;
    size_t base = ((size_t)b * Hc) * HSTRIDE + (size_t)n * Nc;

    sL[tid] = Lm[tid];
    sW[tid] = Wmm[tid];
    // vectorized fp16 load -> fp32 smem
    for (int idx = tid; idx < Hc * (Nc / 8); idx += 256) {
        int h = idx >> 8, c8 = (idx & 255) * 8;
        uint4 u = *(const uint4*)&g_s[base + (size_t)h * HSTRIDE + c8];
        float2 f0 = __half22float2(*(__half2*)&u.x);
        float2 f1 = __half22float2(*(__half2*)&u.y);
        float2 f2 = __half22float2(*(__half2*)&u.z);
        float2 f3 = __half22float2(*(__half2*)&u.w);
        float4* d = (float4*)&s[h * Nc + c8];
        d[0] = make_float4(f0.x, f0.y, f1.x, f1.y);
        d[1] = make_float4(f2.x, f2.y, f3.x, f3.y);
    }
    __syncthreads();

    // ---- pass 1: T = L*S in place; track max ----
    float lmax[16];
#pragma unroll
    for (int g = 0; g < 16; g++) lmax[g] = -3.0e38f;
    for (int j = 0; j < Nc / 256; j++) {
        int m = tid + j * 256;
        float sv[16], tv[16];
#pragma unroll
        for (int h = 0; h < 16; h++) sv[h] = s[h * Nc + m];
#pragma unroll
        for (int g = 0; g < 16; g++) {
            float t = 0.f;
#pragma unroll
            for (int h = 0; h < 16; h++) t = fmaf(sL[g * 16 + h], sv[h], t);
            lmax[g] = fmaxf(lmax[g], t);
            tv[g] = t;
        }
#pragma unroll
        for (int g = 0; g < 16; g++) s[g * Nc + m] = tv[g];
    }
#pragma unroll
    for (int g = 0; g < 16; g++) {
        float v = lmax[g];
        for (int o = 16; o; o >>= 1) v = fmaxf(v, __shfl_xor_sync(0xFFFFFFFFu, v, o));
        if (lane == 0) red[g * 8 + wid] = v;
    }
    __syncthreads();
    if (tid < 16) {
        float v = red[tid * 8];
        for (int w = 1; w < 8; w++) v = fmaxf(v, red[tid * 8 + w]);
        gmax[tid] = v;
    }
    __syncthreads();

    // ---- pass 2: p = exp(T - max) in place; track sum ----
    float gm[16], lsum[16];
#pragma unroll
    for (int g = 0; g < 16; g++) { gm[g] = gmax[g]; lsum[g] = 0.f; }
    for (int j = 0; j < Nc / 256; j++) {
        int m = tid + j * 256;
#pragma unroll
        for (int g = 0; g < 16; g++) {
            float p = exp_fast(s[g * Nc + m] - gm[g]);
            lsum[g] += p;
            s[g * Nc + m] = p;
        }
    }
#pragma unroll
    for (int g = 0; g < 16; g++) {
        float v = lsum[g];
        for (int o = 16; o; o >>= 1) v += __shfl_xor_sync(0xFFFFFFFFu, v, o);
        if (lane == 0) red[g * 8 + wid] = v;
    }
    __syncthreads();
    if (tid < 16) {
        float v = 0.f;
        for (int w = 0; w < 8; w++) v += red[tid * 8 + w];
        ginv[tid] = 1.0f / v;
    }
    __syncthreads();
    sWp[tid] = sW[tid] * ginv[tid & 15];
    __syncthreads();

    // ---- pass 3: U = Wm'*p, write fp16 ----
    for (int j = 0; j < Nc / 256; j++) {
        int m = tid + j * 256;
        float pv[16];
#pragma unroll
        for (int g = 0; g < 16; g++) pv[g] = s[g * Nc + m];
#pragma unroll
        for (int g2 = 0; g2 < 16; g2++) {
            float u = 0.f;
#pragma unroll
            for (int g = 0; g < 16; g++) u = fmaf(sWp[g2 * 16 + g], pv[g], u);
            g_s[base + (size_t)g2 * HSTRIDE + m] = __float2half_rn(u);
        }
    }
}

// =======================================================================
// kernel 4: O = attn @ V per (b,g), fp16 MMA. Block 128(n) x 64(d), K=2048.
// 8 warps as 4(m32) x 2(n32).
// =======================================================================
__global__ void __launch_bounds__(256, 3) av_f16() {
    __shared__ uint32_t Ah2[8][132], Bh2[8][68];
    int bh_ = blockIdx.y;
    const __half* U = g_s + (size_t)bh_ * Nc * Nc;
    const __half* V = g_v + (size_t)bh_ * Nc * HDc;

    int tid = threadIdx.x, lane = tid & 31, w = tid >> 5;
    int wm = (w >> 1) * 32, wn = (w & 1) * 32;
    int row0 = blockIdx.x * 128;

    float acc[2][4][4];
#pragma unroll
    for (int a = 0; a < 2; a++)
#pragma unroll
        for (int b = 0; b < 4; b++)
#pragma unroll
            for (int c = 0; c < 4; c++) acc[a][b][c] = 0.f;

    for (int kt = 0; kt < Nc; kt += 16) {
        // A: U fp16, direct half2-pair copy
        {
            int m = tid >> 1, ko = (tid & 1) * 8;
            uint4 u = *(const uint4*)&U[(size_t)(row0 + m) * Nc + kt + ko];
            Ah2[(ko >> 1) + 0][m] = u.x;
            Ah2[(ko >> 1) + 1][m] = u.y;
            Ah2[(ko >> 1) + 2][m] = u.z;
            Ah2[(ko >> 1) + 3][m] = u.w;
        }
        // B: V fp16 [m][64]; pair across adjacent m rows via byte_perm
        if (tid < 64) {
            int kp = tid >> 3, d8 = (tid & 7) * 8;
            uint4 lo = *(const uint4*)&V[(size_t)(kt + 2 * kp) * HDc + d8];
            uint4 hi = *(const uint4*)&V[(size_t)(kt + 2 * kp + 1) * HDc + d8];
            uint4 s0, s1;
            s0.x = __byte_perm(lo.x, hi.x, 0x5410); s0.y = __byte_perm(lo.x, hi.x, 0x7632);
            s0.z = __byte_perm(lo.y, hi.y, 0x5410); s0.w = __byte_perm(lo.y, hi.y, 0x7632);
            s1.x = __byte_perm(lo.z, hi.z, 0x5410); s1.y = __byte_perm(lo.z, hi.z, 0x7632);
            s1.z = __byte_perm(lo.w, hi.w, 0x5410); s1.w = __byte_perm(lo.w, hi.w, 0x7632);
            *(uint4*)&Bh2[kp][d8] = s0;
            *(uint4*)&Bh2[kp][d8 + 4] = s1;
        }
        __syncthreads();
        int kr = lane & 3, rr = lane >> 2;
        uint32_t ah[2][4], bh[4][2];
#pragma unroll
        for (int mi = 0; mi < 2; mi++) {
            int rb = wm + mi * 16 + rr;
            ah[mi][0] = Ah2[kr][rb];
            ah[mi][1] = Ah2[kr][rb + 8];
            ah[mi][2] = Ah2[kr + 4][rb];
            ah[mi][3] = Ah2[kr + 4][rb + 8];
        }
#pragma unroll
        for (int ni = 0; ni < 4; ni++) {
            int nb = wn + ni * 8 + rr;
            bh[ni][0] = Bh2[kr][nb];
            bh[ni][1] = Bh2[kr + 4][nb];
        }
#pragma unroll
        for (int mi = 0; mi < 2; mi++)
#pragma unroll
            for (int ni = 0; ni < 4; ni++) {
                float* c = acc[mi][ni];
                mma16(c[0], c[1], c[2], c[3], ah[mi][0], ah[mi][1], ah[mi][2], ah[mi][3], bh[ni][0], bh[ni][1]);
            }
        __syncthreads();
    }
    int b = bh_ >> 4, g = bh_ & 15;
#pragma unroll
    for (int mi = 0; mi < 2; mi++) {
        int r0 = row0 + wm + mi * 16 + (lane >> 2);
        int r1 = r0 + 8;
#pragma unroll
        for (int ni = 0; ni < 4; ni++) {
            int d = wn + ni * 8 + (lane & 3) * 2;
            *(__half2*)&g_o[((size_t)b * Nc + r0) * (Hc * HDc) + g * HDc + d] =
                __floats2half2_rn(acc[mi][ni][0], acc[mi][ni][1]);
            *(__half2*)&g_o[((size_t)b * Nc + r1) * (Hc * HDc) + g * HDc + d] =
                __floats2half2_rn(acc[mi][ni][2], acc[mi][ni][3]);
        }
    }
}

// =======================================================================
// kernel 5: out = g_o @ Wo + bo, fp16 MMA. Block 128x128, K=1024.
// =======================================================================
__global__ void __launch_bounds__(256, 2)
out_f16(const float* __restrict__ Wo, const float* __restrict__ bo,
        float* __restrict__ out) {
    __shared__ uint32_t Ah2[8][132], Bh2[8][132];
    int tid = threadIdx.x, lane = tid & 31, w = tid >> 5;
    int wm = (w & 1) * 64, wn = (w >> 1) * 32;
    int row0 = blockIdx.y * 128, col0 = blockIdx.x * 128;

    float acc[4][4][4];
#pragma unroll
    for (int a = 0; a < 4; a++)
#pragma unroll
        for (int b = 0; b < 4; b++)
#pragma unroll
            for (int c = 0; c < 4; c++) acc[a][b][c] = 0.f;

    for (int kt = 0; kt < Hc * HDc; kt += 16) {
        // A: g_o fp16 direct
        {
            int m = tid >> 1, ko = (tid & 1) * 8;
            uint4 u = *(const uint4*)&g_o[(size_t)(row0 + m) * (Hc * HDc) + kt + ko];
            Ah2[(ko >> 1) + 0][m] = u.x;
            Ah2[(ko >> 1) + 1][m] = u.y;
            Ah2[(ko >> 1) + 2][m] = u.z;
            Ah2[(ko >> 1) + 3][m] = u.w;
        }
        // B: Wo fp32 paired across k rows
        {
            int kp = tid >> 5, n4 = (tid & 31) * 4;
            float4 f0 = *(const float4*)&Wo[(size_t)(kt + 2 * kp) * Dc + col0 + n4];
            float4 f1 = *(const float4*)&Wo[(size_t)(kt + 2 * kp + 1) * Dc + col0 + n4];
            uint4 st = {pack2(f0.x, f1.x), pack2(f0.y, f1.y), pack2(f0.z, f1.z), pack2(f0.w, f1.w)};
            *(uint4*)&Bh2[kp][n4] = st;
        }
        __syncthreads();
        int kr = lane & 3, rr = lane >> 2;
        uint32_t ah[4][4], bh[4][2];
#pragma unroll
        for (int mi = 0; mi < 4; mi++) {
            int rb = wm + mi * 16 + rr;
            ah[mi][0] = Ah2[kr][rb];
            ah[mi][1] = Ah2[kr][rb + 8];
            ah[mi][2] = Ah2[kr + 4][rb];
            ah[mi][3] = Ah2[kr + 4][rb + 8];
        }
#pragma unroll
        for (int ni = 0; ni < 4; ni++) {
            int nb = wn + ni * 8 + rr;
            bh[ni][0] = Bh2[kr][nb];
            bh[ni][1] = Bh2[kr + 4][nb];
        }
#pragma unroll
        for (int mi = 0; mi < 4; mi++)
#pragma unroll
            for (int ni = 0; ni < 4; ni++) {
                float* c = acc[mi][ni];
                mma16(c[0], c[1], c[2], c[3], ah[mi][0], ah[mi][1], ah[mi][2], ah[mi][3], bh[ni][0], bh[ni][1]);
            }
        __syncthreads();
    }
#pragma unroll
    for (int mi = 0; mi < 4; mi++) {
        int r0 = row0 + wm + mi * 16 + (lane >> 2);
        int r1 = r0 + 8;
#pragma unroll
        for (int ni = 0; ni < 4; ni++) {
            int c = col0 + wn + ni * 8 + (lane & 3) * 2;
            float2 bias = {bo[c], bo[c + 1]};
            float2 v0 = {acc[mi][ni][0] + bias.x, acc[mi][ni][1] + bias.y};
            float2 v1 = {acc[mi][ni][2] + bias.x, acc[mi][ni][3] + bias.y};
            *(float2*)&out[(size_t)r0 * Dc + c] = v0;
            *(float2*)&out[(size_t)r1 * Dc + c] = v1;
        }
    }
}

// ---------------- launch ----------------
extern "C" void kernel_launch(void* const* d_in, const int* in_sizes, int n_in,
                              void* d_out, int out_size) {
    const float* x  = (const float*)d_in[0];
    const float* Wq = (const float*)d_in[1];
    const float* Wk = (const float*)d_in[2];
    const float* Wv = (const float*)d_in[3];
    const float* L  = (const float*)d_in[4];
    const float* Wm = (const float*)d_in[5];
    const float* Wo = (const float*)d_in[6];
    const float* bo = (const float*)d_in[7];
    float* out = (float*)d_out;
    (void)in_sizes; (void)n_in; (void)out_size;

    proj_f16<<<dim3((Hc * HDc) / 128, (Bc * Nc) / 128, 3), 256>>>(x, Wq, Wk, Wv);

    scores_f16<<<dim3(Nc / 128, Nc / 128, Bc * Hc), 256>>>();

    const int TALK_SMEM = Hc * Nc * sizeof(float);  // 128KB
    (void)cudaFuncSetAttribute(talk_kernel, cudaFuncAttributeMaxDynamicSharedMemorySize, TALK_SMEM);
    talk_kernel<<<Bc * Nc, 256, TALK_SMEM>>>(L, Wm);

    av_f16<<<dim3(Nc / 128, Bc * Hc), 256>>>();

    out_f16<<<dim3(Dc / 128, (Bc * Nc) / 128), 256>>>(Wo, bo, out);
}